// round 5
// baseline (speedup 1.0000x reference)
#include <cuda_runtime.h>
#include <math.h>

// Problem constants
#define BN    64
#define HW    784           // 28*28
#define CN    512
#define S     28            // hw splits -> HWP = 28 per block
#define HWP   28
#define PADW  29            // smem row pad (gcd(29,32)=1 -> conflict-free)

// Scratch (device globals: allocation-free)
__device__ float g_pval[BN * S * CN];
__device__ int   g_pidx[BN * S * CN];
__device__ int   g_idx [BN * CN];

// ---------------------------------------------------------------------------
// Kernel 1: partial argmax. blockIdx = (s, b); thread = channel.
// Coalesced scalar reads; full unroll keeps 28 loads in flight.
// ---------------------------------------------------------------------------
__global__ void __launch_bounds__(CN)
argmax_partial_kernel(const float* __restrict__ x) {
    const int s = blockIdx.x;
    const int b = blockIdx.y;
    const int c = threadIdx.x;
    const int hw0 = s * HWP;

    const size_t base = ((size_t)b * HW + hw0) * CN + c;

    float best = -INFINITY;
    int   bidx = hw0;

    #pragma unroll
    for (int i = 0; i < HWP; ++i) {
        float v = x[base + (size_t)i * CN];
        if (v > best) {            // strict > + ascending i => first occurrence
            best = v;
            bidx = hw0 + i;
        }
    }

    const int o = (b * S + s) * CN + c;
    g_pval[o] = best;
    g_pidx[o] = bidx;
}

// ---------------------------------------------------------------------------
// Kernel 2: combine 28 partials -> final idx[b][c]. Tiny (3.3 MB read).
// Ascending p <=> ascending hw start => first-occurrence preserved.
// ---------------------------------------------------------------------------
__global__ void __launch_bounds__(CN)
combine_kernel() {
    const int b = blockIdx.x;
    const int c = threadIdx.x;

    float best = -INFINITY;
    int   idx  = 0;
    #pragma unroll
    for (int p = 0; p < S; ++p) {
        const int o = (b * S + p) * CN + c;
        float v = g_pval[o];
        if (v > best) { best = v; idx = g_pidx[o]; }
    }
    g_idx[b * CN + c] = idx;
}

// ---------------------------------------------------------------------------
// Kernel 3: apply. blockIdx = (s, b); thread = channel.
// Phase A: cooperatively stage t_p[b, idx[c], hw0..hw0+27] into smem with
//          COALESCED reads (rows are contiguous in hw) -> kills the 32-line
//          divergent gather that bound every previous version.
// Phase B: out[b,hw,c] = relu(x[b,hw,c] * st[c][hw-hw0]); x/out coalesced,
//          smem reads conflict-free (stride 29).
// ---------------------------------------------------------------------------
__global__ void __launch_bounds__(CN)
apply_kernel(const float* __restrict__ x,
             const float* __restrict__ tp,
             float* __restrict__ out) {
    extern __shared__ float st[];              // [CN][PADW] = 59392 B
    __shared__ int sidx[CN];

    const int s = blockIdx.x;
    const int b = blockIdx.y;
    const int c = threadIdx.x;
    const int hw0 = s * HWP;

    sidx[c] = g_idx[b * CN + c];
    __syncthreads();

    // Phase A: stage 512 rows x 28 values. Consecutive threads touch
    // consecutive hw of the same row -> coalesced global reads.
    const size_t tb = (size_t)b * HW;
    #pragma unroll 4
    for (int e = c; e < CN * HWP; e += CN) {
        const int r = e / HWP;
        const int i = e - r * HWP;
        st[r * PADW + i] = tp[(tb + sidx[r]) * HW + hw0 + i];
    }
    __syncthreads();

    // Phase B: multiply + relu. Full unroll -> 28 x-loads batched.
    const size_t base = ((size_t)b * HW + hw0) * CN + c;
    const float* __restrict__ tc = st + c * PADW;

    #pragma unroll
    for (int i = 0; i < HWP; ++i) {
        float xv = x[base + (size_t)i * CN];
        out[base + (size_t)i * CN] = fmaxf(xv * tc[i], 0.0f);
    }
}

// ---------------------------------------------------------------------------
// Launch: inputs [x, t_p]; output fp32 [64,28,28,512]. Graph-capturable
// (attribute set is a host-side property change, not a stream op).
// ---------------------------------------------------------------------------
extern "C" void kernel_launch(void* const* d_in, const int* in_sizes, int n_in,
                              void* d_out, int out_size) {
    (void)in_sizes; (void)n_in; (void)out_size;
    const float* x   = (const float*)d_in[0];
    const float* tp  = (const float*)d_in[1];
    float*       out = (float*)d_out;

    const int smem_bytes = CN * PADW * sizeof(float);   // 59392
    cudaFuncSetAttribute(apply_kernel,
                         cudaFuncAttributeMaxDynamicSharedMemorySize, smem_bytes);

    dim3 grid(S, BN);
    argmax_partial_kernel<<<grid, CN>>>(x);
    combine_kernel<<<BN, CN>>>();
    apply_kernel<<<grid, CN, smem_bytes>>>(x, tp, out);
}

// round 6
// speedup vs baseline: 1.4638x; 1.4638x over previous
#include <cuda_runtime.h>
#include <math.h>

// Problem constants
#define BN    64
#define HW    784           // 28*28
#define CN    512
#define SA    28            // argmax hw splits  (HWPA = 28)
#define HWPA  28
#define SB    14            // apply hw splits   (HWPB = 56; 56*4B = 224 ≡ 0 mod 16)
#define HWPB  56
#define HWPB4 14            // HWPB / 4

// Scratch for partial argmax (device globals: allocation-free)
// Layout [BN][SA][CN]; ascending s <=> ascending hw start.
__device__ float g_pval[BN * SA * CN];
__device__ int   g_pidx[BN * SA * CN];

// ---------------------------------------------------------------------------
// Kernel 1: partial argmax (R5 config — measured 19.5us, DRAM 67%).
// blockIdx = (s, b); thread = channel. Coalesced scalar reads, full unroll.
// ---------------------------------------------------------------------------
__global__ void __launch_bounds__(CN)
argmax_partial_kernel(const float* __restrict__ x) {
    const int s = blockIdx.x;
    const int b = blockIdx.y;
    const int c = threadIdx.x;
    const int hw0 = s * HWPA;

    const size_t base = ((size_t)b * HW + hw0) * CN + c;

    float best = -INFINITY;
    int   bidx = hw0;

    #pragma unroll
    for (int i = 0; i < HWPA; ++i) {
        float v = x[base + (size_t)i * CN];
        if (v > best) {            // strict > + ascending i => first occurrence
            best = v;
            bidx = hw0 + i;
        }
    }

    const int o = (b * SA + s) * CN + c;
    g_pval[o] = best;
    g_pidx[o] = bidx;
}

// ---------------------------------------------------------------------------
// Kernel 2: combine 28 partials (prologue; [b]-slab is L2-hot across the
// batch's 14 blocks), then
//   out[b,hw,c] = relu(x[b,hw,c] * t_p[b, idx[b,c], hw])
// Template stream read as float4 per thread (proven R2 shape); x/out scalar
// coalesced along c. Grid (64,14)=896 blocks -> 2 clean full-occupancy waves.
// ---------------------------------------------------------------------------
__global__ void __launch_bounds__(CN)
apply_kernel(const float* __restrict__ x,
             const float* __restrict__ tp,
             float* __restrict__ out) {
    const int b = blockIdx.x;
    const int s = blockIdx.y;
    const int c = threadIdx.x;

    // Combine partials: ascending p (== ascending hw) + strict > keeps the
    // earliest spatial index on equal maxima (matches jnp.argmax).
    float best = -INFINITY;
    int   idx  = 0;
    {
        const size_t o0 = (size_t)b * SA * CN + c;
        #pragma unroll 7
        for (int p = 0; p < SA; ++p) {
            float v = g_pval[o0 + (size_t)p * CN];
            if (v > best) {
                best = v;
                idx  = g_pidx[o0 + (size_t)p * CN];
            }
        }
    }

    // Selected template row slice: t_p[b, idx, s*56 .. s*56+55]
    // Row pitch 3136B and slice offset 224B are 16B multiples -> float4-safe.
    const float4* __restrict__ trow4 =
        (const float4*)(tp + ((size_t)b * HW + (size_t)idx) * HW + s * HWPB);

    const size_t base = ((size_t)b * HW + (size_t)s * HWPB) * CN + c;

    #pragma unroll 4
    for (int j = 0; j < HWPB4; ++j) {
        const float4 t4 = __ldg(trow4 + j);
        const size_t o  = base + (size_t)(4 * j) * CN;

        float x0 = x[o];
        float x1 = x[o + (size_t)CN];
        float x2 = x[o + (size_t)(2 * CN)];
        float x3 = x[o + (size_t)(3 * CN)];

        out[o]                    = fmaxf(x0 * t4.x, 0.0f);
        out[o + (size_t)CN]       = fmaxf(x1 * t4.y, 0.0f);
        out[o + (size_t)(2 * CN)] = fmaxf(x2 * t4.z, 0.0f);
        out[o + (size_t)(3 * CN)] = fmaxf(x3 * t4.w, 0.0f);
    }
}

// ---------------------------------------------------------------------------
// Launch: inputs [x, t_p]; output fp32 [64,28,28,512]. Graph-capturable.
// ---------------------------------------------------------------------------
extern "C" void kernel_launch(void* const* d_in, const int* in_sizes, int n_in,
                              void* d_out, int out_size) {
    (void)in_sizes; (void)n_in; (void)out_size;
    const float* x   = (const float*)d_in[0];
    const float* tp  = (const float*)d_in[1];
    float*       out = (float*)d_out;

    dim3 gridA(SA, BN);
    argmax_partial_kernel<<<gridA, CN>>>(x);

    dim3 gridB(BN, SB);
    apply_kernel<<<gridB, CN>>>(x, tp, out);
}